// round 3
// baseline (speedup 1.0000x reference)
#include <cuda_runtime.h>
#include <cstdint>
#include <cstddef>

// ---------------------------------------------------------------------------
// Neural CDE classifier, ONE persistent clustered kernel, f32x2 packed math.
// grid = 128 CTAs = 16 clusters x 8, 256 thr/CTA, 1 CTA/SM.
// Cluster owns 32 batch elements; W2 (2048x128) row-sliced 256 rows/CTA.
// Per RK4 substep: L0 slice -> allgather(h0) -> L1 slice -> allgather(h1,dup)
// -> L2 slice GEMM (f32x2) + tanh + dx contraction -> allgather(k) -> combine.
// dt cancels exactly; times input unused.
// ---------------------------------------------------------------------------

typedef unsigned long long ull;

namespace {
constexpr int NSTEPS = 2047;

// shared memory layout (float offsets)
constexpr int OFF_W2T = 0;        // [128][256] vf_W2 slice, k-major
constexpr int OFF_W1T = 32768;    // [128][16]  vf_W1 slice, k-major scalar
constexpr int OFF_W0T = 34816;    // [64][16]   vf_W0 slice, k-major scalar
constexpr int OFF_B0  = 35840;    // [16]
constexpr int OFF_B1  = 35856;    // [16]
constexpr int OFF_B2  = 35872;    // [256]
constexpr int OFF_Y   = 36128;    // [64][32]
constexpr int OFF_YIN = 38176;    // [64][32]
constexpr int OFF_KC  = 40224;    // [64][32]
constexpr int OFF_H0  = 42272;    // [128][32]
constexpr int OFF_H1D = 46368;    // [128][64]  h1 batch-duplicated (f32x2)
constexpr int OFF_DXP = 54560;    // [16][32] f32x2 pairs: (dx[2dp],dx[2dp+1]) per b
constexpr int SMEM_FLOATS = 55584;
constexpr int SMEM_BYTES  = SMEM_FLOATS * 4;   // 222336 B
}

__device__ __forceinline__ uint32_t s2u(const void* p) {
    return (uint32_t)__cvta_generic_to_shared(p);
}
__device__ __forceinline__ uint32_t mapa_u(uint32_t laddr, int rank) {
    uint32_t r;
    asm("mapa.shared::cluster.u32 %0, %1, %2;" : "=r"(r) : "r"(laddr), "r"(rank));
    return r;
}
__device__ __forceinline__ void st_cluster64(uint32_t raddr, ull v) {
    asm volatile("st.shared::cluster.b64 [%0], %1;" :: "r"(raddr), "l"(v) : "memory");
}
__device__ __forceinline__ void cluster_sync_() {
    asm volatile("barrier.cluster.arrive.aligned;" ::: "memory");
    asm volatile("barrier.cluster.wait.aligned;" ::: "memory");
}
__device__ __forceinline__ void ffma2(ull& d, ull a, ull b) {
    asm("fma.rn.f32x2 %0, %1, %2, %0;" : "+l"(d) : "l"(a), "l"(b));
}
__device__ __forceinline__ ull dup2(float v) {
    ull r; asm("mov.b64 %0, {%1, %1};" : "=l"(r) : "f"(v)); return r;
}
__device__ __forceinline__ ull pack2(float a, float b) {
    ull r; asm("mov.b64 %0, {%1, %2};" : "=l"(r) : "f"(a), "f"(b)); return r;
}
__device__ __forceinline__ float2 unpk(ull v) {
    float2 f; asm("mov.b64 {%0, %1}, %2;" : "=f"(f.x), "=f"(f.y) : "l"(v)); return f;
}

__device__ __forceinline__ float tanh_f(float x) {
    float ax = fabsf(x);
    float e  = __expf(-2.0f * ax);
    float r  = __fdividef(1.0f - e, 1.0f + e);
    return copysignf(r, x);
}
__device__ __forceinline__ float gelu_f(float x) {
    float x3 = x * x * x;
    float t  = tanh_f(0.7978845608028654f * fmaf(0.044715f, x3, x));
    return 0.5f * x * (1.0f + t);
}

__global__ void __launch_bounds__(256, 1)
ncde_kernel(const float* __restrict__ xs,
            const float* __restrict__ eW0, const float* __restrict__ eb0,
            const float* __restrict__ eW1, const float* __restrict__ eb1,
            const float* __restrict__ eW2, const float* __restrict__ eb2,
            const float* __restrict__ vW0, const float* __restrict__ vb0,
            const float* __restrict__ vW1, const float* __restrict__ vb1,
            const float* __restrict__ vW2, const float* __restrict__ vb2,
            const float* __restrict__ dW,  const float* __restrict__ db,
            float* __restrict__ out)
{
    extern __shared__ float sm[];
    const int tid   = threadIdx.x;
    const int rank  = blockIdx.x & 7;
    const int bbase = (blockIdx.x >> 3) * 32;

    float* sW2T = sm + OFF_W2T;
    float* sW1T = sm + OFF_W1T;
    float* sW0T = sm + OFF_W0T;
    float* sB0  = sm + OFF_B0;
    float* sB1  = sm + OFF_B1;
    float* sB2  = sm + OFF_B2;
    float* sY   = sm + OFF_Y;
    float* sYIN = sm + OFF_YIN;
    float* sKC  = sm + OFF_KC;
    float* sH0  = sm + OFF_H0;
    float* sH1D = sm + OFF_H1D;
    float* sDXP = sm + OFF_DXP;

    // per-rank DSMEM address deltas (mapa is affine in the local address)
    uint32_t rdelta[8];
    {
        uint32_t base = s2u(sm);
        #pragma unroll
        for (int r = 0; r < 8; ++r) rdelta[r] = mapa_u(base, r) - base;
    }

    // per-thread xs mapping: thread owns (b = tid>>3, d = (tid&7)*4 .. +3)
    const int xb  = tid >> 3;
    const int xdq = tid & 7;
    const float* xsrow = xs + (size_t)(bbase + xb) * 2048 * 32 + xdq * 4;

    float xc0, xc1, xc2, xc3;  // current xs values (thread-owned)
    {
        float4 v = *reinterpret_cast<const float4*>(xsrow);
        xc0 = v.x; xc1 = v.y; xc2 = v.z; xc3 = v.w;
        // stage xs0 d-major into sKC scratch for the encoder
        sKC[(xdq * 4 + 0) * 32 + xb] = v.x;
        sKC[(xdq * 4 + 1) * 32 + xb] = v.y;
        sKC[(xdq * 4 + 2) * 32 + xb] = v.z;
        sKC[(xdq * 4 + 3) * 32 + xb] = v.w;
    }

    // ---- encoder weights transposed into W2T scratch ----
    float* sE0 = sW2T;          // [32][128]
    float* sE1 = sW2T + 4096;   // [128][128]
    float* sE2 = sW2T + 20480;  // [128][64]
    for (int i = tid; i < 4096;  i += 256) { int r = i & 127, kk = i >> 7; sE0[i] = eW0[r * 32  + kk]; }
    for (int i = tid; i < 16384; i += 256) { int r = i & 127, kk = i >> 7; sE1[i] = eW1[r * 128 + kk]; }
    for (int i = tid; i < 8192;  i += 256) { int r = i & 63,  kk = i >> 6; sE2[i] = eW2[r * 128 + kk]; }
    __syncthreads();

    // ---- encoder (replicated per CTA): xs0(sKC) -> sH0 -> sH1D[:4096] -> sY
    {
        int b = tid & 31, rbase = (tid >> 5) * 16;
        float acc[16];
        #pragma unroll
        for (int j = 0; j < 16; ++j) acc[j] = eb0[rbase + j];
        for (int kk = 0; kk < 32; ++kk) {
            float x = sKC[kk * 32 + b];
            #pragma unroll
            for (int j = 0; j < 16; ++j) acc[j] = fmaf(sE0[kk * 128 + rbase + j], x, acc[j]);
        }
        #pragma unroll
        for (int j = 0; j < 16; ++j) sH0[(rbase + j) * 32 + b] = fmaxf(acc[j], 0.0f);
    }
    __syncthreads();
    {
        int b = tid & 31, rbase = (tid >> 5) * 16;
        float acc[16];
        #pragma unroll
        for (int j = 0; j < 16; ++j) acc[j] = eb1[rbase + j];
        for (int kk = 0; kk < 128; ++kk) {
            float x = sH0[kk * 32 + b];
            #pragma unroll
            for (int j = 0; j < 16; ++j) acc[j] = fmaf(sE1[kk * 128 + rbase + j], x, acc[j]);
        }
        #pragma unroll
        for (int j = 0; j < 16; ++j) sH1D[(rbase + j) * 32 + b] = fmaxf(acc[j], 0.0f);
    }
    __syncthreads();
    {
        int b = tid & 31, rbase = (tid >> 5) * 8;
        float acc[8];
        #pragma unroll
        for (int j = 0; j < 8; ++j) acc[j] = eb2[rbase + j];
        for (int kk = 0; kk < 128; ++kk) {
            float x = sH1D[kk * 32 + b];
            #pragma unroll
            for (int j = 0; j < 8; ++j) acc[j] = fmaf(sE2[kk * 64 + rbase + j], x, acc[j]);
        }
        #pragma unroll
        for (int j = 0; j < 8; ++j) sY[(rbase + j) * 32 + b] = acc[j];
    }
    __syncthreads();

    // ---- load vf weight slices (overwrites encoder scratch) ----
    for (int i = tid; i < 32768; i += 256) {
        int rloc = i & 255, kk = i >> 8;
        sW2T[i] = vW2[(size_t)(rank * 256 + rloc) * 128 + kk];
    }
    for (int i = tid; i < 2048; i += 256) {
        int r = i & 15, kk = i >> 4;
        sW1T[i] = vW1[(rank * 16 + r) * 128 + kk];
    }
    for (int i = tid; i < 1024; i += 256) {
        int r = i & 15, kk = i >> 4;
        sW0T[i] = vW0[(rank * 16 + r) * 64 + kk];
    }
    if (tid < 16)      sB0[tid]      = vb0[rank * 16 + tid];
    else if (tid < 32) sB1[tid - 16] = vb1[rank * 16 + tid - 16];
    sB2[tid] = vb2[rank * 256 + tid];
    cluster_sync_();

    // ---- per-thread invariants ----
    const int rl = tid >> 4;      // L0/L1 row (0..15)
    const int pl = tid & 15;      // L0/L1 batch-pair (b = 2*pl, 2*pl+1)
    const int bh = tid & 7;       // L2 batch quad (b = 4*bh..+3)
    const int dg = (tid >> 3) & 3;// L2 d-group
    const int m_ = tid >> 5;      // L2 local m (0..7) == warp id

    float b2r[8];
    #pragma unroll
    for (int j = 0; j < 8; ++j) b2r[j] = sB2[m_ * 32 + dg * 8 + j];
    const float b0s = sB0[rl];
    const float b1s = sB1[rl];

    const uint32_t aH0  = s2u(&sH0[(rank * 16 + rl) * 32 + pl * 2]);
    const uint32_t aH1  = s2u(&sH1D[(rank * 16 + rl) * 64 + pl * 4]);
    const uint32_t aKC  = s2u(&sKC[(rank * 8 + m_) * 32 + bh * 4]);
    const float* w2base = sW2T + m_ * 32 + dg * 8;
    const float* x2base = sH1D + bh * 8;

    // ---- main RK4 scan ----
    for (int t = 0; t < NSTEPS; ++t) {
        float4 xn = *reinterpret_cast<const float4*>(xsrow + (size_t)(t + 1) * 32);
        float ks0, ks1, ks2, ks3, ks4, ks5, ks6, ks7;

        #pragma unroll
        for (int s = 0; s < 4; ++s) {
            const float* yin = (s == 0) ? sY : sYIN;

            // ---- L0: h0 slice (16 rows) = gelu(W0s @ yin + b0), batch-paired
            {
                ull acc = dup2(b0s);
                #pragma unroll 8
                for (int kk = 0; kk < 64; ++kk) {
                    ull wd = dup2(sW0T[kk * 16 + rl]);
                    ull x  = *reinterpret_cast<const ull*>(&yin[kk * 32 + pl * 2]);
                    ffma2(acc, wd, x);
                }
                float2 a = unpk(acc);
                ull g = pack2(gelu_f(a.x), gelu_f(a.y));
                #pragma unroll
                for (int r = 0; r < 8; ++r) st_cluster64(aH0 + rdelta[r], g);
            }

            if (s == 0) {
                float d0 = xn.x - xc0, d1 = xn.y - xc1, d2 = xn.z - xc2, d3 = xn.w - xc3;
                xc0 = xn.x; xc1 = xn.y; xc2 = xn.z; xc3 = xn.w;
                *reinterpret_cast<ull*>(&sDXP[(xdq * 2 * 32 + xb) * 2])       = pack2(d0, d1);
                *reinterpret_cast<ull*>(&sDXP[((xdq * 2 + 1) * 32 + xb) * 2]) = pack2(d2, d3);
            }
            cluster_sync_();  // B1: h0 (and dx) complete everywhere

            // ---- L1: h1 slice (16 rows) = gelu(W1s @ h0 + b1), store duplicated
            {
                ull acc = dup2(b1s);
                #pragma unroll 8
                for (int kk = 0; kk < 128; ++kk) {
                    ull wd = dup2(sW1T[kk * 16 + rl]);
                    ull x  = *reinterpret_cast<const ull*>(&sH0[kk * 32 + pl * 2]);
                    ffma2(acc, wd, x);
                }
                float2 a = unpk(acc);
                ull g0 = dup2(gelu_f(a.x));
                ull g1 = dup2(gelu_f(a.y));
                #pragma unroll
                for (int r = 0; r < 8; ++r) {
                    st_cluster64(aH1 + rdelta[r], g0);
                    st_cluster64(aH1 + 8 + rdelta[r], g1);
                }
            }
            cluster_sync_();  // B2: h1 complete everywhere

            // ---- L2: u = tanh(W2s @ h1 + b2); k slice = sum_d u*dx (packed)
            {
                ull acc[4][4];
                #pragma unroll
                for (int j = 0; j < 4; ++j)
                    #pragma unroll
                    for (int i = 0; i < 4; ++i) acc[j][i] = 0ull;

                #pragma unroll 2
                for (int kk = 0; kk < 128; ++kk) {
                    ulonglong2 wA = *reinterpret_cast<const ulonglong2*>(w2base + kk * 256);
                    ulonglong2 wB = *reinterpret_cast<const ulonglong2*>(w2base + kk * 256 + 4);
                    ulonglong2 xA = *reinterpret_cast<const ulonglong2*>(x2base + kk * 64);
                    ulonglong2 xB = *reinterpret_cast<const ulonglong2*>(x2base + kk * 64 + 4);
                    ffma2(acc[0][0], wA.x, xA.x); ffma2(acc[0][1], wA.x, xA.y);
                    ffma2(acc[0][2], wA.x, xB.x); ffma2(acc[0][3], wA.x, xB.y);
                    ffma2(acc[1][0], wA.y, xA.x); ffma2(acc[1][1], wA.y, xA.y);
                    ffma2(acc[1][2], wA.y, xB.x); ffma2(acc[1][3], wA.y, xB.y);
                    ffma2(acc[2][0], wB.x, xA.x); ffma2(acc[2][1], wB.x, xA.y);
                    ffma2(acc[2][2], wB.x, xB.x); ffma2(acc[2][3], wB.x, xB.y);
                    ffma2(acc[3][0], wB.y, xA.x); ffma2(acc[3][1], wB.y, xA.y);
                    ffma2(acc[3][2], wB.y, xB.x); ffma2(acc[3][3], wB.y, xB.y);
                }

                float kp[4] = {0.0f, 0.0f, 0.0f, 0.0f};
                #pragma unroll
                for (int j = 0; j < 4; ++j) {
                    float ba = b2r[2 * j], bb = b2r[2 * j + 1];
                    #pragma unroll
                    for (int i = 0; i < 4; ++i) {
                        float2 u  = unpk(acc[j][i]);
                        float2 dx = *reinterpret_cast<const float2*>(
                            &sDXP[((dg * 4 + j) * 32 + bh * 4 + i) * 2]);
                        float u0 = tanh_f(u.x + ba);
                        float u1 = tanh_f(u.y + bb);
                        kp[i] = fmaf(u0, dx.x, fmaf(u1, dx.y, kp[i]));
                    }
                }
                #pragma unroll
                for (int i = 0; i < 4; ++i) {
                    kp[i] += __shfl_xor_sync(0xffffffffu, kp[i], 8);
                    kp[i] += __shfl_xor_sync(0xffffffffu, kp[i], 16);
                }
                if (dg == 0) {
                    ull k01 = pack2(kp[0], kp[1]);
                    ull k23 = pack2(kp[2], kp[3]);
                    #pragma unroll
                    for (int r = 0; r < 8; ++r) {
                        st_cluster64(aKC + rdelta[r], k01);
                        st_cluster64(aKC + 8 + rdelta[r], k23);
                    }
                }
            }
            cluster_sync_();  // B3: k complete everywhere

            // ---- RK4 combine (thread owns elements [tid*8, tid*8+8))
            {
                const int f = tid * 8;
                float4 k0 = *reinterpret_cast<float4*>(&sKC[f]);
                float4 k1 = *reinterpret_cast<float4*>(&sKC[f + 4]);
                if (s == 0) {
                    ks0 = k0.x; ks1 = k0.y; ks2 = k0.z; ks3 = k0.w;
                    ks4 = k1.x; ks5 = k1.y; ks6 = k1.z; ks7 = k1.w;
                } else {
                    const float w_s = (s == 3) ? 1.0f : 2.0f;
                    ks0 = fmaf(w_s, k0.x, ks0); ks1 = fmaf(w_s, k0.y, ks1);
                    ks2 = fmaf(w_s, k0.z, ks2); ks3 = fmaf(w_s, k0.w, ks3);
                    ks4 = fmaf(w_s, k1.x, ks4); ks5 = fmaf(w_s, k1.y, ks5);
                    ks6 = fmaf(w_s, k1.z, ks6); ks7 = fmaf(w_s, k1.w, ks7);
                }
                float4 y0 = *reinterpret_cast<float4*>(&sY[f]);
                float4 y1 = *reinterpret_cast<float4*>(&sY[f + 4]);
                if (s < 3) {
                    const float c = (s == 2) ? 1.0f : 0.5f;
                    float4 a, b;
                    a.x = fmaf(c, k0.x, y0.x); a.y = fmaf(c, k0.y, y0.y);
                    a.z = fmaf(c, k0.z, y0.z); a.w = fmaf(c, k0.w, y0.w);
                    b.x = fmaf(c, k1.x, y1.x); b.y = fmaf(c, k1.y, y1.y);
                    b.z = fmaf(c, k1.z, y1.z); b.w = fmaf(c, k1.w, y1.w);
                    *reinterpret_cast<float4*>(&sYIN[f])     = a;
                    *reinterpret_cast<float4*>(&sYIN[f + 4]) = b;
                } else {
                    const float sx = 1.0f / 6.0f;
                    y0.x = fmaf(sx, ks0, y0.x); y0.y = fmaf(sx, ks1, y0.y);
                    y0.z = fmaf(sx, ks2, y0.z); y0.w = fmaf(sx, ks3, y0.w);
                    y1.x = fmaf(sx, ks4, y1.x); y1.y = fmaf(sx, ks5, y1.y);
                    y1.z = fmaf(sx, ks6, y1.z); y1.w = fmaf(sx, ks7, y1.w);
                    *reinterpret_cast<float4*>(&sY[f])     = y0;
                    *reinterpret_cast<float4*>(&sY[f + 4]) = y1;
                }
            }
            __syncthreads();
        }
    }

    // ---- decoder + sigmoid (rank 0 CTA) ----
    if (rank == 0 && tid < 32) {
        float acc = db[0];
        #pragma unroll 8
        for (int r = 0; r < 64; ++r) acc = fmaf(dW[r], sY[r * 32 + tid], acc);
        out[bbase + tid] = __fdividef(1.0f, 1.0f + __expf(-acc));
    }
}

extern "C" void kernel_launch(void* const* d_in, const int* in_sizes, int n_in,
                              void* d_out, int out_size) {
    (void)in_sizes; (void)n_in; (void)out_size;
    const float* xs  = (const float*)d_in[1];
    const float* eW0 = (const float*)d_in[2];
    const float* eb0 = (const float*)d_in[3];
    const float* eW1 = (const float*)d_in[4];
    const float* eb1 = (const float*)d_in[5];
    const float* eW2 = (const float*)d_in[6];
    const float* eb2 = (const float*)d_in[7];
    const float* vW0 = (const float*)d_in[8];
    const float* vb0 = (const float*)d_in[9];
    const float* vW1 = (const float*)d_in[10];
    const float* vb1 = (const float*)d_in[11];
    const float* vW2 = (const float*)d_in[12];
    const float* vb2 = (const float*)d_in[13];
    const float* dW  = (const float*)d_in[14];
    const float* db  = (const float*)d_in[15];
    float* out = (float*)d_out;

    cudaFuncSetAttribute(ncde_kernel, cudaFuncAttributeMaxDynamicSharedMemorySize, SMEM_BYTES);

    cudaLaunchConfig_t cfg = {};
    cfg.gridDim  = dim3(128, 1, 1);
    cfg.blockDim = dim3(256, 1, 1);
    cfg.dynamicSmemBytes = SMEM_BYTES;
    cfg.stream = 0;
    cudaLaunchAttribute attrs[1];
    attrs[0].id = cudaLaunchAttributeClusterDimension;
    attrs[0].val.clusterDim.x = 8;
    attrs[0].val.clusterDim.y = 1;
    attrs[0].val.clusterDim.z = 1;
    cfg.attrs = attrs;
    cfg.numAttrs = 1;

    cudaLaunchKernelEx(&cfg, ncde_kernel,
                       xs, eW0, eb0, eW1, eb1, eW2, eb2,
                       vW0, vb0, vW1, vb1, vW2, vb2, dW, db, out);
}

// round 4
// speedup vs baseline: 1.4549x; 1.4549x over previous
#include <cuda_runtime.h>
#include <cstdint>
#include <cstddef>

// ---------------------------------------------------------------------------
// Neural CDE classifier, ONE persistent clustered kernel.
// grid = 128 CTAs = 16 clusters x 8, 512 thr/CTA (4 warps/SMSP), 1 CTA/SM.
// Cluster owns 32 batch elements; W2 (2048x128) row-sliced 256 rows/CTA.
// Per RK4 substep: L0 slice -> allgather(h0) -> L1 slice -> allgather(h1)
// -> L2 slice GEMM + tanh + dx contraction -> allgather(k) -> combine.
// dt cancels exactly; times input unused. All math scalar fp32 FFMA.
// ---------------------------------------------------------------------------

typedef unsigned long long ull;

namespace {
constexpr int NSTEPS = 2047;

// shared memory layout (float offsets)
constexpr int OFF_W2T = 0;        // [128][256] vf_W2 slice, k-major
constexpr int OFF_W1T = 32768;    // [16][128]  vf_W1 slice, row-major
constexpr int OFF_W0T = 34816;    // [16][64]   vf_W0 slice, row-major
constexpr int OFF_B0  = 35840;    // [16]
constexpr int OFF_B1  = 35856;    // [16]
constexpr int OFF_B2  = 35872;    // [256]
constexpr int OFF_Y   = 36128;    // [64][32]
constexpr int OFF_YIN = 38176;    // [64][32]
constexpr int OFF_KC  = 40224;    // [64][32]
constexpr int OFF_H0  = 42272;    // [128][32]
constexpr int OFF_H1  = 46368;    // [128][32]
constexpr int OFF_DX  = 50464;    // [32][32]  d-major
constexpr int SMEM_FLOATS = 51488;
constexpr int SMEM_BYTES  = SMEM_FLOATS * 4;   // 205952 B
}

__device__ __forceinline__ uint32_t s2u(const void* p) {
    return (uint32_t)__cvta_generic_to_shared(p);
}
__device__ __forceinline__ uint32_t mapa_u(uint32_t laddr, int rank) {
    uint32_t r;
    asm("mapa.shared::cluster.u32 %0, %1, %2;" : "=r"(r) : "r"(laddr), "r"(rank));
    return r;
}
__device__ __forceinline__ void st_cluster32(uint32_t raddr, float v) {
    asm volatile("st.shared::cluster.f32 [%0], %1;" :: "r"(raddr), "f"(v) : "memory");
}
__device__ __forceinline__ void st_cluster64(uint32_t raddr, float a, float b) {
    ull v;
    asm("mov.b64 %0, {%1, %2};" : "=l"(v) : "f"(a), "f"(b));
    asm volatile("st.shared::cluster.b64 [%0], %1;" :: "r"(raddr), "l"(v) : "memory");
}
__device__ __forceinline__ void cluster_sync_() {
    asm volatile("barrier.cluster.arrive.aligned;" ::: "memory");
    asm volatile("barrier.cluster.wait.aligned;" ::: "memory");
}
__device__ __forceinline__ float tanh_f(float x) {
    float ax = fabsf(x);
    float e  = __expf(-2.0f * ax);
    float r  = __fdividef(1.0f - e, 1.0f + e);
    return copysignf(r, x);
}
__device__ __forceinline__ float gelu_f(float x) {
    float x3 = x * x * x;
    float t  = tanh_f(0.7978845608028654f * fmaf(0.044715f, x3, x));
    return 0.5f * x * (1.0f + t);
}

__global__ void __launch_bounds__(512, 1)
ncde_kernel(const float* __restrict__ xs,
            const float* __restrict__ eW0, const float* __restrict__ eb0,
            const float* __restrict__ eW1, const float* __restrict__ eb1,
            const float* __restrict__ eW2, const float* __restrict__ eb2,
            const float* __restrict__ vW0, const float* __restrict__ vb0,
            const float* __restrict__ vW1, const float* __restrict__ vb1,
            const float* __restrict__ vW2, const float* __restrict__ vb2,
            const float* __restrict__ dW,  const float* __restrict__ db,
            float* __restrict__ out)
{
    extern __shared__ float sm[];
    const int tid   = threadIdx.x;
    const int lane  = tid & 31;
    const int wid   = tid >> 5;          // 0..15
    const int rank  = blockIdx.x & 7;
    const int bbase = (blockIdx.x >> 3) * 32;

    float* sW2T = sm + OFF_W2T;
    float* sW1T = sm + OFF_W1T;
    float* sW0T = sm + OFF_W0T;
    float* sB0  = sm + OFF_B0;
    float* sB1  = sm + OFF_B1;
    float* sB2  = sm + OFF_B2;
    float* sY   = sm + OFF_Y;
    float* sYIN = sm + OFF_YIN;
    float* sKC  = sm + OFF_KC;
    float* sH0  = sm + OFF_H0;
    float* sH1  = sm + OFF_H1;
    float* sDX  = sm + OFF_DX;

    // per-rank DSMEM address deltas (mapa is affine in the local address)
    uint32_t rdelta[8];
    {
        uint32_t base = s2u(sm);
        #pragma unroll
        for (int r = 0; r < 8; ++r) rdelta[r] = mapa_u(base, r) - base;
    }

    // per-thread xs mapping: thread owns (b = tid>>4, d = 2*(tid&15), +1)
    const int xb  = tid >> 4;
    const int xd2 = tid & 15;
    const float* xsrow = xs + (size_t)(bbase + xb) * 2048 * 32 + xd2 * 2;

    float xc0, xc1;
    {
        float2 v = *reinterpret_cast<const float2*>(xsrow);
        xc0 = v.x; xc1 = v.y;
        sKC[(2 * xd2) * 32 + xb]     = v.x;   // stage xs0 d-major for encoder
        sKC[(2 * xd2 + 1) * 32 + xb] = v.y;
    }

    // ---- encoder weights transposed into W2T scratch ----
    float* sE0 = sW2T;          // [32][128]
    float* sE1 = sW2T + 4096;   // [128][128]
    float* sE2 = sW2T + 20480;  // [128][64]
    for (int i = tid; i < 4096;  i += 512) { int r = i & 127, kk = i >> 7; sE0[i] = eW0[r * 32  + kk]; }
    for (int i = tid; i < 16384; i += 512) { int r = i & 127, kk = i >> 7; sE1[i] = eW1[r * 128 + kk]; }
    for (int i = tid; i < 8192;  i += 512) { int r = i & 63,  kk = i >> 6; sE2[i] = eW2[r * 128 + kk]; }
    __syncthreads();

    // ---- encoder (replicated per CTA): sKC(xs0) -> sH0 -> sH1 -> sY ----
    {
        int b = lane, rbase = wid * 8;
        float acc[8];
        #pragma unroll
        for (int j = 0; j < 8; ++j) acc[j] = eb0[rbase + j];
        for (int kk = 0; kk < 32; ++kk) {
            float x = sKC[kk * 32 + b];
            #pragma unroll
            for (int j = 0; j < 8; ++j) acc[j] = fmaf(sE0[kk * 128 + rbase + j], x, acc[j]);
        }
        #pragma unroll
        for (int j = 0; j < 8; ++j) sH0[(rbase + j) * 32 + b] = fmaxf(acc[j], 0.0f);
    }
    __syncthreads();
    {
        int b = lane, rbase = wid * 8;
        float acc[8];
        #pragma unroll
        for (int j = 0; j < 8; ++j) acc[j] = eb1[rbase + j];
        for (int kk = 0; kk < 128; ++kk) {
            float x = sH0[kk * 32 + b];
            #pragma unroll
            for (int j = 0; j < 8; ++j) acc[j] = fmaf(sE1[kk * 128 + rbase + j], x, acc[j]);
        }
        #pragma unroll
        for (int j = 0; j < 8; ++j) sH1[(rbase + j) * 32 + b] = fmaxf(acc[j], 0.0f);
    }
    __syncthreads();
    {
        int b = lane, rbase = wid * 4;
        float acc[4];
        #pragma unroll
        for (int j = 0; j < 4; ++j) acc[j] = eb2[rbase + j];
        for (int kk = 0; kk < 128; ++kk) {
            float x = sH1[kk * 32 + b];
            #pragma unroll
            for (int j = 0; j < 4; ++j) acc[j] = fmaf(sE2[kk * 64 + rbase + j], x, acc[j]);
        }
        #pragma unroll
        for (int j = 0; j < 4; ++j) sY[(rbase + j) * 32 + b] = acc[j];
    }
    __syncthreads();

    // ---- load vf weight slices (overwrites encoder scratch) ----
    for (int i = tid; i < 32768; i += 512) {
        int rloc = i & 255, kk = i >> 8;
        sW2T[i] = vW2[(size_t)(rank * 256 + rloc) * 128 + kk];
    }
    for (int i = tid; i < 2048; i += 512) {
        int kk = i & 127, r = i >> 7;
        sW1T[i] = vW1[(rank * 16 + r) * 128 + kk];
    }
    for (int i = tid; i < 1024; i += 512) {
        int kk = i & 63, r = i >> 6;
        sW0T[i] = vW0[(rank * 16 + r) * 64 + kk];
    }
    if (tid < 16)      sB0[tid]      = vb0[rank * 16 + tid];
    else if (tid < 32) sB1[tid - 16] = vb1[rank * 16 + tid - 16];
    if (tid < 256)     sB2[tid]      = vb2[rank * 256 + tid];
    cluster_sync_();

    // ---- per-thread invariants ----
    // L0/L1: warp = row (0..15), lane = batch
    const float b0s = sB0[wid];
    const float b1s = sB1[wid];
    const uint32_t aH0 = s2u(&sH0[(rank * 16 + wid) * 32 + lane]);
    const uint32_t aH1 = s2u(&sH1[(rank * 16 + wid) * 32 + lane]);

    // L2: m = wid>>1 (local m 0..7), bh = wid&1, dg = lane>>2, bql = lane&3
    const int m_  = wid >> 1;
    const int bh  = wid & 1;
    const int dg  = lane >> 2;
    const int bq  = bh * 4 + (lane & 3);     // batch quad 0..7 -> b = bq*4..+3
    float b2r[4];
    #pragma unroll
    for (int j = 0; j < 4; ++j) b2r[j] = sB2[m_ * 32 + dg * 4 + j];
    const float* w2base = sW2T + m_ * 32 + dg * 4;
    const float* x2base = sH1 + bq * 4;
    const float* dxbase = sDX + (dg * 4) * 32 + bq * 4;
    const uint32_t aKC = s2u(&sKC[(rank * 8 + m_) * 32 + bq * 4]);

    // ---- main RK4 scan ----
    for (int t = 0; t < NSTEPS; ++t) {
        float2 xn = *reinterpret_cast<const float2*>(xsrow + (size_t)(t + 1) * 32);
        float ks0, ks1, ks2, ks3;

        #pragma unroll
        for (int s = 0; s < 4; ++s) {
            const float* yin = (s == 0) ? sY : sYIN;

            // ---- L0: h0[row=wid][b=lane] = gelu(W0s @ yin + b0) ----
            {
                float a = b0s;
                const float* wrow = sW0T + wid * 64;
                #pragma unroll
                for (int k4 = 0; k4 < 16; ++k4) {
                    float4 w4 = *reinterpret_cast<const float4*>(wrow + k4 * 4);
                    a = fmaf(w4.x, yin[(k4 * 4 + 0) * 32 + lane], a);
                    a = fmaf(w4.y, yin[(k4 * 4 + 1) * 32 + lane], a);
                    a = fmaf(w4.z, yin[(k4 * 4 + 2) * 32 + lane], a);
                    a = fmaf(w4.w, yin[(k4 * 4 + 3) * 32 + lane], a);
                }
                a = gelu_f(a);
                #pragma unroll
                for (int r = 0; r < 8; ++r) st_cluster32(aH0 + rdelta[r], a);
            }

            if (s == 0) {
                float d0 = xn.x - xc0, d1 = xn.y - xc1;
                xc0 = xn.x; xc1 = xn.y;
                sDX[(2 * xd2) * 32 + xb]     = d0;
                sDX[(2 * xd2 + 1) * 32 + xb] = d1;
            }
            cluster_sync_();  // B1: h0 (and dx) complete everywhere

            // ---- L1: h1[row=wid][b=lane] = gelu(W1s @ h0 + b1) ----
            {
                float a = b1s;
                const float* wrow = sW1T + wid * 128;
                #pragma unroll 8
                for (int k4 = 0; k4 < 32; ++k4) {
                    float4 w4 = *reinterpret_cast<const float4*>(wrow + k4 * 4);
                    a = fmaf(w4.x, sH0[(k4 * 4 + 0) * 32 + lane], a);
                    a = fmaf(w4.y, sH0[(k4 * 4 + 1) * 32 + lane], a);
                    a = fmaf(w4.z, sH0[(k4 * 4 + 2) * 32 + lane], a);
                    a = fmaf(w4.w, sH0[(k4 * 4 + 3) * 32 + lane], a);
                }
                a = gelu_f(a);
                #pragma unroll
                for (int r = 0; r < 8; ++r) st_cluster32(aH1 + rdelta[r], a);
            }
            cluster_sync_();  // B2: h1 complete everywhere

            // ---- L2: u = tanh(W2s @ h1 + b2); k slice = sum_d u*dx ----
            {
                float acc[4][4];
                #pragma unroll
                for (int j = 0; j < 4; ++j)
                    #pragma unroll
                    for (int i = 0; i < 4; ++i) acc[j][i] = 0.0f;

                #pragma unroll 4
                for (int kk = 0; kk < 128; ++kk) {
                    float4 w4 = *reinterpret_cast<const float4*>(w2base + kk * 256);
                    float4 x4 = *reinterpret_cast<const float4*>(x2base + kk * 32);
                    float wv[4] = {w4.x, w4.y, w4.z, w4.w};
                    float xv[4] = {x4.x, x4.y, x4.z, x4.w};
                    #pragma unroll
                    for (int j = 0; j < 4; ++j)
                        #pragma unroll
                        for (int i = 0; i < 4; ++i)
                            acc[j][i] = fmaf(wv[j], xv[i], acc[j][i]);
                }

                float kp[4] = {0.0f, 0.0f, 0.0f, 0.0f};
                #pragma unroll
                for (int j = 0; j < 4; ++j) {
                    float bias = b2r[j];
                    float4 dx4 = *reinterpret_cast<const float4*>(dxbase + j * 32);
                    float u0 = tanh_f(acc[j][0] + bias);
                    float u1 = tanh_f(acc[j][1] + bias);
                    float u2 = tanh_f(acc[j][2] + bias);
                    float u3 = tanh_f(acc[j][3] + bias);
                    kp[0] = fmaf(u0, dx4.x, kp[0]);
                    kp[1] = fmaf(u1, dx4.y, kp[1]);
                    kp[2] = fmaf(u2, dx4.z, kp[2]);
                    kp[3] = fmaf(u3, dx4.w, kp[3]);
                }
                // reduce over the 8 d-groups (lane bits 2,3,4)
                #pragma unroll
                for (int i = 0; i < 4; ++i) {
                    kp[i] += __shfl_xor_sync(0xffffffffu, kp[i], 4);
                    kp[i] += __shfl_xor_sync(0xffffffffu, kp[i], 8);
                    kp[i] += __shfl_xor_sync(0xffffffffu, kp[i], 16);
                }
                if (dg == 0) {
                    #pragma unroll
                    for (int r = 0; r < 8; ++r) {
                        st_cluster64(aKC + rdelta[r],     kp[0], kp[1]);
                        st_cluster64(aKC + 8 + rdelta[r], kp[2], kp[3]);
                    }
                }
            }
            cluster_sync_();  // B3: k complete everywhere

            // ---- RK4 combine (thread owns y elements [tid*4, tid*4+4)) ----
            {
                const int f = tid * 4;
                float4 k4 = *reinterpret_cast<float4*>(&sKC[f]);
                if (s == 0) {
                    ks0 = k4.x; ks1 = k4.y; ks2 = k4.z; ks3 = k4.w;
                } else {
                    const float w_s = (s == 3) ? 1.0f : 2.0f;
                    ks0 = fmaf(w_s, k4.x, ks0); ks1 = fmaf(w_s, k4.y, ks1);
                    ks2 = fmaf(w_s, k4.z, ks2); ks3 = fmaf(w_s, k4.w, ks3);
                }
                float4 y4 = *reinterpret_cast<float4*>(&sY[f]);
                if (s < 3) {
                    const float c = (s == 2) ? 1.0f : 0.5f;
                    float4 a;
                    a.x = fmaf(c, k4.x, y4.x); a.y = fmaf(c, k4.y, y4.y);
                    a.z = fmaf(c, k4.z, y4.z); a.w = fmaf(c, k4.w, y4.w);
                    *reinterpret_cast<float4*>(&sYIN[f]) = a;
                } else {
                    const float sx = 1.0f / 6.0f;
                    y4.x = fmaf(sx, ks0, y4.x); y4.y = fmaf(sx, ks1, y4.y);
                    y4.z = fmaf(sx, ks2, y4.z); y4.w = fmaf(sx, ks3, y4.w);
                    *reinterpret_cast<float4*>(&sY[f]) = y4;
                }
            }
            __syncthreads();
        }
    }

    // ---- decoder + sigmoid (rank 0 CTA) ----
    if (rank == 0 && tid < 32) {
        float acc = db[0];
        #pragma unroll 8
        for (int r = 0; r < 64; ++r) acc = fmaf(dW[r], sY[r * 32 + tid], acc);
        out[bbase + tid] = __fdividef(1.0f, 1.0f + __expf(-acc));
    }
}

extern "C" void kernel_launch(void* const* d_in, const int* in_sizes, int n_in,
                              void* d_out, int out_size) {
    (void)in_sizes; (void)n_in; (void)out_size;
    const float* xs  = (const float*)d_in[1];
    const float* eW0 = (const float*)d_in[2];
    const float* eb0 = (const float*)d_in[3];
    const float* eW1 = (const float*)d_in[4];
    const float* eb1 = (const float*)d_in[5];
    const float* eW2 = (const float*)d_in[6];
    const float* eb2 = (const float*)d_in[7];
    const float* vW0 = (const float*)d_in[8];
    const float* vb0 = (const float*)d_in[9];
    const float* vW1 = (const float*)d_in[10];
    const float* vb1 = (const float*)d_in[11];
    const float* vW2 = (const float*)d_in[12];
    const float* vb2 = (const float*)d_in[13];
    const float* dW  = (const float*)d_in[14];
    const float* db  = (const float*)d_in[15];
    float* out = (float*)d_out;

    cudaFuncSetAttribute(ncde_kernel, cudaFuncAttributeMaxDynamicSharedMemorySize, SMEM_BYTES);

    cudaLaunchConfig_t cfg = {};
    cfg.gridDim  = dim3(128, 1, 1);
    cfg.blockDim = dim3(512, 1, 1);
    cfg.dynamicSmemBytes = SMEM_BYTES;
    cfg.stream = 0;
    cudaLaunchAttribute attrs[1];
    attrs[0].id = cudaLaunchAttributeClusterDimension;
    attrs[0].val.clusterDim.x = 8;
    attrs[0].val.clusterDim.y = 1;
    attrs[0].val.clusterDim.z = 1;
    cfg.attrs = attrs;
    cfg.numAttrs = 1;

    cudaLaunchKernelEx(&cfg, ncde_kernel,
                       xs, eW0, eb0, eW1, eb1, eW2, eb2,
                       vW0, vb0, vW1, vb1, vW2, vb2, dW, db, out);
}